// round 3
// baseline (speedup 1.0000x reference)
#include <cuda_runtime.h>
#include <math.h>

#define N_TOK   49
#define DIM     128
#define NHEADS  4
#define HD      32
#define NWIN    64
#define THREADS 384

// smem layout (float offsets):
#define X_OFF    0        // 6272 floats: x tile 49x128
#define Q_OFF    6272     // 6272: q [h][n][d] (pre-scaled)
#define KT_OFF   12544    // 6272: kT [h][d][n]
#define V_OFF    18816    // 6272: v [h][n][d]
#define MASK_OFF 25088    // 2401: mask window
#define REL_OFF  27489    // 676:  rel_table (169x4)
#define RIDX_B   ((27489 + 676) * 4)   // byte offset of 2401 uint8 rel indices
#define SMEM_BYTES (RIDX_B + 2401 + 11)  // pad a touch

// packed f32x2 FMA: acc.{lo,hi} += a.{lo,hi} * b.{lo,hi}
#define FFMA2(acc, a, b) \
    asm("fma.rn.f32x2 %0, %1, %2, %0;" : "+l"(acc) : "l"(a), "l"(b))

__device__ __forceinline__ float hsum2(unsigned long long p) {
    float lo, hi;
    asm("mov.b64 {%0, %1}, %2;" : "=f"(lo), "=f"(hi) : "l"(p));
    return lo + hi;
}

__global__ __launch_bounds__(THREADS, 1)
void win_attn_kernel(const float* __restrict__ x,
                     const float* __restrict__ mask,
                     const float* __restrict__ W,        // (384,128)
                     const float* __restrict__ bvec,     // (384,)
                     const float* __restrict__ rel_table,// (169,4)
                     float* __restrict__ out)
{
    extern __shared__ float sm[];
    float* xs     = sm + X_OFF;
    float* q_s    = sm + Q_OFF;
    float* kT_s   = sm + KT_OFF;
    float* v_s    = sm + V_OFF;
    float* mask_s = sm + MASK_OFF;
    float* rel_s  = sm + REL_OFF;
    unsigned char* ridx_s = (unsigned char*)sm + RIDX_B;

    const int b = blockIdx.x;
    const int t = threadIdx.x;

    // ---- phase 0: stage x, mask, rel_table, rel indices (concurrent, no alias) ----
    {
        const float4* xg  = (const float4*)(x + (size_t)b * (N_TOK * DIM));
        float4*       xs4 = (float4*)xs;
        #pragma unroll
        for (int i = t; i < (N_TOK * DIM) / 4; i += THREADS) xs4[i] = xg[i];

        const float* mw = mask + (size_t)(b & (NWIN - 1)) * (N_TOK * N_TOK);
        for (int i = t; i < N_TOK * N_TOK; i += THREADS) {
            mask_s[i] = mw[i];
            const int n = i / N_TOK, m = i - n * N_TOK;
            const int dh = n / 7 - m / 7 + 6;
            const int dw = n % 7 - m % 7 + 6;
            ridx_s[i] = (unsigned char)(dh * 13 + dw);
        }
        for (int i = t; i < 169 * NHEADS; i += THREADS) rel_s[i] = rel_table[i];
    }
    __syncthreads();

    // ---- phase 1: QKV projection ----
    // thread t: column pair (c0, c0+1), row half. Halves overlap at row 24
    // (computed twice, identical value -> benign write race, no guards needed).
    {
        const int th   = (t < 192) ? t : (t - 192);
        const int half = (t < 192) ? 0 : 1;
        const int c0   = 2 * th;
        const int row0 = half * 24;          // 0..24 or 24..48

        unsigned long long acc[2][25];
        #pragma unroll
        for (int c = 0; c < 2; c++)
            #pragma unroll
            for (int r = 0; r < 25; r++) acc[c][r] = 0ULL;

        const ulonglong2* w0p = (const ulonglong2*)(W + (size_t)c0 * DIM);
        const ulonglong2* w1p = (const ulonglong2*)(W + (size_t)(c0 + 1) * DIM);
        const ulonglong2* xs2 = (const ulonglong2*)xs;   // [n*32 + kk] = 4 floats

        for (int kk = 0; kk < DIM / 4; kk++) {
            const ulonglong2 w0 = __ldg(&w0p[kk]);
            const ulonglong2 w1 = __ldg(&w1p[kk]);
            #pragma unroll
            for (int r = 0; r < 25; r++) {
                const ulonglong2 xv = xs2[(row0 + r) * (DIM / 4) + kk]; // LDS.128 bcast
                FFMA2(acc[0][r], xv.x, w0.x);
                FFMA2(acc[0][r], xv.y, w0.y);
                FFMA2(acc[1][r], xv.x, w1.x);
                FFMA2(acc[1][r], xv.y, w1.y);
            }
        }

        const float scale = 0.17677669529663687f;  // 1/sqrt(32) folded into q
        #pragma unroll
        for (int c = 0; c < 2; c++) {
            const int o     = c0 + c;
            const int h     = o / 96;
            const int rem   = o - h * 96;
            const int d     = rem / 3;
            const int which = rem - d * 3;
            const float bo  = bvec[o];
            #pragma unroll
            for (int r = 0; r < 25; r++) {
                const int n = row0 + r;
                const float val = hsum2(acc[c][r]) + bo;
                if (which == 0)      q_s [(h * N_TOK + n) * HD + d]    = val * scale;
                else if (which == 1) kT_s[(h * HD + d) * N_TOK + n]    = val;
                else                 v_s [(h * N_TOK + n) * HD + d]    = val;
            }
        }
    }
    __syncthreads();

    // ---- phase 2: attention, one warp per (head, row) ----
    const int lane = t & 31;
    const int wid  = t >> 5;
    const bool valid1 = (lane + 32) < N_TOK;
    float* outb = out + (size_t)b * (N_TOK * DIM);

    for (int r = wid; r < NHEADS * N_TOK; r += THREADS / 32) {
        const int h = r / N_TOK;
        const int n = r - h * N_TOK;
        const int m0 = lane;
        const int m1 = valid1 ? (lane + 32) : 0;

        const float* qrow = q_s + (h * N_TOK + n) * HD;
        const float* kTb  = kT_s + h * HD * N_TOK;

        float s0 = 0.f, s1 = 0.f;
        #pragma unroll
        for (int dd = 0; dd < HD; dd++) {
            const float qd = qrow[dd];
            s0 = fmaf(qd, kTb[dd * N_TOK + m0], s0);
            s1 = fmaf(qd, kTb[dd * N_TOK + m1], s1);
        }
        s0 += rel_s[(int)ridx_s[n * N_TOK + m0] * NHEADS + h] + mask_s[n * N_TOK + m0];
        if (valid1)
            s1 += rel_s[(int)ridx_s[n * N_TOK + lane + 32] * NHEADS + h]
                + mask_s[n * N_TOK + lane + 32];
        else
            s1 = -1e30f;

        float mx = fmaxf(s0, s1);
        #pragma unroll
        for (int off = 16; off; off >>= 1) mx = fmaxf(mx, __shfl_xor_sync(0xffffffffu, mx, off));
        float p0 = __expf(s0 - mx);
        float p1 = valid1 ? __expf(s1 - mx) : 0.f;
        float sum = p0 + p1;
        #pragma unroll
        for (int off = 16; off; off >>= 1) sum += __shfl_xor_sync(0xffffffffu, sum, off);
        const float inv = 1.0f / sum;
        p0 *= inv; p1 *= inv;

        float acc = 0.f;
        const float* vb = v_s + h * N_TOK * HD + lane;
        #pragma unroll
        for (int m = 0; m < N_TOK; m++) {
            const float pm = __shfl_sync(0xffffffffu, (m < 32) ? p0 : p1, m & 31);
            acc = fmaf(pm, vb[m * HD], acc);
        }
        outb[n * DIM + h * HD + lane] = acc;
    }
}

extern "C" void kernel_launch(void* const* d_in, const int* in_sizes, int n_in,
                              void* d_out, int out_size)
{
    const float* x    = (const float*)d_in[0];
    const float* mask = (const float*)d_in[1];
    const float* W    = (const float*)d_in[2];
    const float* bvec = (const float*)d_in[3];
    const float* rel  = (const float*)d_in[4];
    float* out = (float*)d_out;

    cudaFuncSetAttribute(win_attn_kernel,
                         cudaFuncAttributeMaxDynamicSharedMemorySize, SMEM_BYTES);
    win_attn_kernel<<<4096, THREADS, SMEM_BYTES>>>(x, mask, W, bvec, rel, out);
}